// round 2
// baseline (speedup 1.0000x reference)
#include <cuda_runtime.h>

// Problem dimensions (fixed by the reference).
#define B_DIM 8
#define C_DIM 2048
#define T_DIM 1024
#define S_DIM 1024
#define E_DIM 1024

// SGEMM tiling: 128x128 block tile, K-tile 8, 8x8 per-thread micro-tile, 256 threads.
#define BM 128
#define BN 128
#define BK 8
#define TM 8
#define TN 8

// Device-global scratch (allocation-free rule).
__device__ float g_wT[(size_t)C_DIM * E_DIM];          // w_h2e transposed: [C][E]
__device__ float g_Y[(size_t)B_DIM * T_DIM * E_DIM];   // conved_combined: [B][T][E]
__device__ float g_A2[(size_t)B_DIM * T_DIM * E_DIM];  // attended:        [B][T][E]

// Shared compute core: 8x8 outer product over the BK slice of the current buffer.
#define GEMM_COMPUTE(buf)                                                 \
  _Pragma("unroll")                                                       \
  for (int kk = 0; kk < BK; ++kk) {                                       \
    float af[TM], bf[TN];                                                 \
    *(float4*)(af)     = *(const float4*)(&As[buf][kk][rb]);              \
    *(float4*)(af + 4) = *(const float4*)(&As[buf][kk][rb + 4]);          \
    *(float4*)(bf)     = *(const float4*)(&Bs[buf][kk][cb]);              \
    *(float4*)(bf + 4) = *(const float4*)(&Bs[buf][kk][cb + 4]);          \
    _Pragma("unroll")                                                     \
    for (int i = 0; i < TM; ++i) {                                        \
      _Pragma("unroll")                                                   \
      for (int j = 0; j < TN; ++j) acc[i][j] += af[i] * bf[j];            \
    }                                                                     \
  }

// ---------------------------------------------------------------------------
// w_h2e [E][C] -> g_wT [C][E]  (so GEMM1's B tiles are coalesced K-major loads)
// ---------------------------------------------------------------------------
__global__ void transpose_wh2e(const float* __restrict__ w) {
  __shared__ float tile[32][33];
  const int cx = blockIdx.x * 32, ey = blockIdx.y * 32;
  const int tx = threadIdx.x, ty = threadIdx.y;
#pragma unroll
  for (int i = 0; i < 32; i += 8)
    tile[ty + i][tx] = w[(size_t)(ey + ty + i) * C_DIM + cx + tx];
  __syncthreads();
#pragma unroll
  for (int i = 0; i < 32; i += 8)
    g_wT[(size_t)(cx + ty + i) * E_DIM + ey + tx] = tile[tx][ty + i];
}

// ---------------------------------------------------------------------------
// GEMM1: Y[b,t,e] = (sum_c conved[b,c,t] * w_h2e[e,c] + b_h2e[e] + x[b,t,e]) * scale
// A = conved (K-major: [k=c][m=t], t contiguous), B = g_wT (K-major: [k=c][n=e])
// ---------------------------------------------------------------------------
__global__ __launch_bounds__(256, 2) void gemm1_kernel(
    const float* __restrict__ conved, const float* __restrict__ x,
    const float* __restrict__ b_h2e, const float* __restrict__ scale_p) {
  __shared__ float As[2][BK][BM];
  __shared__ float Bs[2][BK][BN];
  const int tid = threadIdx.x;
  const int b = blockIdx.z;
  const int mblk = blockIdx.y * BM;
  const int nblk = blockIdx.x * BN;
  const float* Ab = conved + (size_t)b * C_DIM * T_DIM;

  const int lr = tid >> 5;          // 0..7  (k within tile)
  const int lc = (tid & 31) << 2;   // 0..124 (m/n within tile, float4)
  const int rb = (tid >> 4) * TM;
  const int cb = (tid & 15) * TN;

  float acc[TM][TN];
#pragma unroll
  for (int i = 0; i < TM; ++i)
#pragma unroll
    for (int j = 0; j < TN; ++j) acc[i][j] = 0.f;

  float4 a_reg = *(const float4*)(Ab + (size_t)lr * T_DIM + mblk + lc);
  float4 b_reg = *(const float4*)(g_wT + (size_t)lr * E_DIM + nblk + lc);
  *(float4*)&As[0][lr][lc] = a_reg;
  *(float4*)&Bs[0][lr][lc] = b_reg;
  __syncthreads();

  int cur = 0;
  for (int k0 = BK; k0 < C_DIM; k0 += BK) {
    a_reg = *(const float4*)(Ab + (size_t)(k0 + lr) * T_DIM + mblk + lc);
    b_reg = *(const float4*)(g_wT + (size_t)(k0 + lr) * E_DIM + nblk + lc);
    GEMM_COMPUTE(cur);
    cur ^= 1;
    *(float4*)&As[cur][lr][lc] = a_reg;
    *(float4*)&Bs[cur][lr][lc] = b_reg;
    __syncthreads();
  }
  GEMM_COMPUTE(cur);

  const float s = scale_p[0];
#pragma unroll
  for (int i = 0; i < TM; ++i) {
    const int t = mblk + rb + i;
    const size_t rowoff = (size_t)b * T_DIM * E_DIM + (size_t)t * E_DIM + nblk + cb;
#pragma unroll
    for (int j4 = 0; j4 < TN; j4 += 4) {
      float4 xv = *(const float4*)(x + rowoff + j4);
      float4 bv = *(const float4*)(b_h2e + nblk + cb + j4);
      float4 o;
      o.x = (acc[i][j4 + 0] + bv.x + xv.x) * s;
      o.y = (acc[i][j4 + 1] + bv.y + xv.y) * s;
      o.z = (acc[i][j4 + 2] + bv.z + xv.z) * s;
      o.w = (acc[i][j4 + 3] + bv.w + xv.w) * s;
      *(float4*)(g_Y + rowoff + j4) = o;
    }
  }
}

// ---------------------------------------------------------------------------
// GEMM2: energy[b,t,s] = sum_e Y[b,t,e] * enc_conved[b,s,e]   (NT GEMM)
// Both operands row-major K(e)-contiguous -> transposed smem stores.
// ---------------------------------------------------------------------------
__global__ __launch_bounds__(256, 2) void gemm2_kernel(
    const float* __restrict__ enc_conved, float* __restrict__ energy) {
  __shared__ float As[2][BK][BM];
  __shared__ float Bs[2][BK][BN];
  const int tid = threadIdx.x;
  const int b = blockIdx.z;
  const int mblk = blockIdx.y * BM;  // t
  const int nblk = blockIdx.x * BN;  // s
  const float* Ab = g_Y + (size_t)b * T_DIM * E_DIM;
  const float* Bb = enc_conved + (size_t)b * S_DIM * E_DIM;

  const int lm = tid >> 1;          // 0..127
  const int lk = (tid & 1) << 2;    // 0 or 4
  const int rb = (tid >> 4) * TM;
  const int cb = (tid & 15) * TN;

  float acc[TM][TN];
#pragma unroll
  for (int i = 0; i < TM; ++i)
#pragma unroll
    for (int j = 0; j < TN; ++j) acc[i][j] = 0.f;

  float4 a_reg = *(const float4*)(Ab + (size_t)(mblk + lm) * E_DIM + lk);
  float4 b_reg = *(const float4*)(Bb + (size_t)(nblk + lm) * E_DIM + lk);
  As[0][lk + 0][lm] = a_reg.x; As[0][lk + 1][lm] = a_reg.y;
  As[0][lk + 2][lm] = a_reg.z; As[0][lk + 3][lm] = a_reg.w;
  Bs[0][lk + 0][lm] = b_reg.x; Bs[0][lk + 1][lm] = b_reg.y;
  Bs[0][lk + 2][lm] = b_reg.z; Bs[0][lk + 3][lm] = b_reg.w;
  __syncthreads();

  int cur = 0;
  for (int k0 = BK; k0 < E_DIM; k0 += BK) {
    a_reg = *(const float4*)(Ab + (size_t)(mblk + lm) * E_DIM + k0 + lk);
    b_reg = *(const float4*)(Bb + (size_t)(nblk + lm) * E_DIM + k0 + lk);
    GEMM_COMPUTE(cur);
    cur ^= 1;
    As[cur][lk + 0][lm] = a_reg.x; As[cur][lk + 1][lm] = a_reg.y;
    As[cur][lk + 2][lm] = a_reg.z; As[cur][lk + 3][lm] = a_reg.w;
    Bs[cur][lk + 0][lm] = b_reg.x; Bs[cur][lk + 1][lm] = b_reg.y;
    Bs[cur][lk + 2][lm] = b_reg.z; Bs[cur][lk + 3][lm] = b_reg.w;
    __syncthreads();
  }
  GEMM_COMPUTE(cur);

#pragma unroll
  for (int i = 0; i < TM; ++i) {
    const int t = mblk + rb + i;
    const size_t rowoff = (size_t)b * T_DIM * S_DIM + (size_t)t * S_DIM + nblk + cb;
#pragma unroll
    for (int j4 = 0; j4 < TN; j4 += 4) {
      float4 o;
      o.x = acc[i][j4 + 0]; o.y = acc[i][j4 + 1];
      o.z = acc[i][j4 + 2]; o.w = acc[i][j4 + 3];
      *(float4*)(energy + rowoff + j4) = o;
    }
  }
}

// ---------------------------------------------------------------------------
// In-place row softmax over S. One block per (b,t) row.
// ---------------------------------------------------------------------------
__global__ __launch_bounds__(256) void softmax_kernel(float* __restrict__ att) {
  const size_t row = blockIdx.x;
  float* p = att + row * S_DIM;
  const int tid = threadIdx.x;
  float4 v = reinterpret_cast<float4*>(p)[tid];

  float m = fmaxf(fmaxf(v.x, v.y), fmaxf(v.z, v.w));
#pragma unroll
  for (int o = 16; o; o >>= 1) m = fmaxf(m, __shfl_xor_sync(0xffffffffu, m, o));
  __shared__ float redm[8];
  if ((tid & 31) == 0) redm[tid >> 5] = m;
  __syncthreads();
  float mall = redm[0];
#pragma unroll
  for (int i = 1; i < 8; ++i) mall = fmaxf(mall, redm[i]);

  v.x = __expf(v.x - mall); v.y = __expf(v.y - mall);
  v.z = __expf(v.z - mall); v.w = __expf(v.w - mall);
  float s = v.x + v.y + v.z + v.w;
#pragma unroll
  for (int o = 16; o; o >>= 1) s += __shfl_xor_sync(0xffffffffu, s, o);
  __shared__ float reds[8];
  if ((tid & 31) == 0) reds[tid >> 5] = s;
  __syncthreads();
  float sall = 0.f;
#pragma unroll
  for (int i = 0; i < 8; ++i) sall += reds[i];
  const float inv = 1.0f / sall;
  v.x *= inv; v.y *= inv; v.z *= inv; v.w *= inv;
  reinterpret_cast<float4*>(p)[tid] = v;
}

// ---------------------------------------------------------------------------
// GEMM3: A2[b,t,e] = sum_s attn[b,t,s] * enc_combined[b,s,e]
// A = attn row-major (K=s contiguous), B = enc_combined K-major ([k=s][n=e]).
// ---------------------------------------------------------------------------
__global__ __launch_bounds__(256, 2) void gemm3_kernel(
    const float* __restrict__ enc_combined, const float* __restrict__ attn) {
  __shared__ float As[2][BK][BM];
  __shared__ float Bs[2][BK][BN];
  const int tid = threadIdx.x;
  const int b = blockIdx.z;
  const int mblk = blockIdx.y * BM;  // t
  const int nblk = blockIdx.x * BN;  // e
  const float* Ab = attn + (size_t)b * T_DIM * S_DIM;
  const float* Bb = enc_combined + (size_t)b * S_DIM * E_DIM;

  const int lm = tid >> 1;
  const int lk = (tid & 1) << 2;
  const int lr = tid >> 5;
  const int lc = (tid & 31) << 2;
  const int rb = (tid >> 4) * TM;
  const int cb = (tid & 15) * TN;

  float acc[TM][TN];
#pragma unroll
  for (int i = 0; i < TM; ++i)
#pragma unroll
    for (int j = 0; j < TN; ++j) acc[i][j] = 0.f;

  float4 a_reg = *(const float4*)(Ab + (size_t)(mblk + lm) * S_DIM + lk);
  float4 b_reg = *(const float4*)(Bb + (size_t)lr * E_DIM + nblk + lc);
  As[0][lk + 0][lm] = a_reg.x; As[0][lk + 1][lm] = a_reg.y;
  As[0][lk + 2][lm] = a_reg.z; As[0][lk + 3][lm] = a_reg.w;
  *(float4*)&Bs[0][lr][lc] = b_reg;
  __syncthreads();

  int cur = 0;
  for (int k0 = BK; k0 < S_DIM; k0 += BK) {
    a_reg = *(const float4*)(Ab + (size_t)(mblk + lm) * S_DIM + k0 + lk);
    b_reg = *(const float4*)(Bb + (size_t)(k0 + lr) * E_DIM + nblk + lc);
    GEMM_COMPUTE(cur);
    cur ^= 1;
    As[cur][lk + 0][lm] = a_reg.x; As[cur][lk + 1][lm] = a_reg.y;
    As[cur][lk + 2][lm] = a_reg.z; As[cur][lk + 3][lm] = a_reg.w;
    *(float4*)&Bs[cur][lr][lc] = b_reg;
    __syncthreads();
  }
  GEMM_COMPUTE(cur);

#pragma unroll
  for (int i = 0; i < TM; ++i) {
    const int t = mblk + rb + i;
    const size_t rowoff = (size_t)b * T_DIM * E_DIM + (size_t)t * E_DIM + nblk + cb;
#pragma unroll
    for (int j4 = 0; j4 < TN; j4 += 4) {
      float4 o;
      o.x = acc[i][j4 + 0]; o.y = acc[i][j4 + 1];
      o.z = acc[i][j4 + 2]; o.w = acc[i][j4 + 3];
      *(float4*)(g_A2 + rowoff + j4) = o;
    }
  }
}

// ---------------------------------------------------------------------------
// GEMM4: out2[b,c,t] = conved[b,c,t] + b_e2h[c] + sum_e w_e2h[c,e] * A2[b,t,e]
// M=c, N=t, K=e. Both operands row-major K-contiguous (NT GEMM).
// ---------------------------------------------------------------------------
__global__ __launch_bounds__(256, 2) void gemm4_kernel(
    const float* __restrict__ w_e2h, const float* __restrict__ b_e2h,
    const float* __restrict__ conved, float* __restrict__ out2) {
  __shared__ float As[2][BK][BM];
  __shared__ float Bs[2][BK][BN];
  const int tid = threadIdx.x;
  const int b = blockIdx.z;
  const int mblk = blockIdx.y * BM;  // c
  const int nblk = blockIdx.x * BN;  // t
  const float* Ab = w_e2h;                              // [c][e]
  const float* Bb = g_A2 + (size_t)b * T_DIM * E_DIM;   // [t][e]

  const int lm = tid >> 1;
  const int lk = (tid & 1) << 2;
  const int rb = (tid >> 4) * TM;
  const int cb = (tid & 15) * TN;

  float acc[TM][TN];
#pragma unroll
  for (int i = 0; i < TM; ++i)
#pragma unroll
    for (int j = 0; j < TN; ++j) acc[i][j] = 0.f;

  float4 a_reg = *(const float4*)(Ab + (size_t)(mblk + lm) * E_DIM + lk);
  float4 b_reg = *(const float4*)(Bb + (size_t)(nblk + lm) * E_DIM + lk);
  As[0][lk + 0][lm] = a_reg.x; As[0][lk + 1][lm] = a_reg.y;
  As[0][lk + 2][lm] = a_reg.z; As[0][lk + 3][lm] = a_reg.w;
  Bs[0][lk + 0][lm] = b_reg.x; Bs[0][lk + 1][lm] = b_reg.y;
  Bs[0][lk + 2][lm] = b_reg.z; Bs[0][lk + 3][lm] = b_reg.w;
  __syncthreads();

  int cur = 0;
  for (int k0 = BK; k0 < E_DIM; k0 += BK) {
    a_reg = *(const float4*)(Ab + (size_t)(mblk + lm) * E_DIM + k0 + lk);
    b_reg = *(const float4*)(Bb + (size_t)(nblk + lm) * E_DIM + k0 + lk);
    GEMM_COMPUTE(cur);
    cur ^= 1;
    As[cur][lk + 0][lm] = a_reg.x; As[cur][lk + 1][lm] = a_reg.y;
    As[cur][lk + 2][lm] = a_reg.z; As[cur][lk + 3][lm] = a_reg.w;
    Bs[cur][lk + 0][lm] = b_reg.x; Bs[cur][lk + 1][lm] = b_reg.y;
    Bs[cur][lk + 2][lm] = b_reg.z; Bs[cur][lk + 3][lm] = b_reg.w;
    __syncthreads();
  }
  GEMM_COMPUTE(cur);

#pragma unroll
  for (int i = 0; i < TM; ++i) {
    const int c = mblk + rb + i;
    const float bias = __ldg(b_e2h + c);
    const size_t rowoff = (size_t)b * C_DIM * T_DIM + (size_t)c * T_DIM + nblk + cb;
#pragma unroll
    for (int j4 = 0; j4 < TN; j4 += 4) {
      float4 cv = *(const float4*)(conved + rowoff + j4);
      float4 o;
      o.x = acc[i][j4 + 0] + cv.x + bias;
      o.y = acc[i][j4 + 1] + cv.y + bias;
      o.z = acc[i][j4 + 2] + cv.z + bias;
      o.w = acc[i][j4 + 3] + cv.w + bias;
      *(float4*)(out2 + rowoff + j4) = o;
    }
  }
}

// ---------------------------------------------------------------------------
// Launch: 6 kernels on the capture stream, no syncs, no allocations.
// Output layout: [attention (B*T*S floats)] then [attended_combined (B*C*T)].
// ---------------------------------------------------------------------------
extern "C" void kernel_launch(void* const* d_in, const int* in_sizes, int n_in,
                              void* d_out, int out_size) {
  const float* conved       = (const float*)d_in[0];
  const float* enc_conved   = (const float*)d_in[1];
  const float* enc_combined = (const float*)d_in[2];
  const float* x            = (const float*)d_in[3];
  const float* scale        = (const float*)d_in[4];
  const float* w_h2e        = (const float*)d_in[5];
  const float* b_h2e        = (const float*)d_in[6];
  const float* w_e2h        = (const float*)d_in[7];
  const float* b_e2h        = (const float*)d_in[8];

  float* attn = (float*)d_out;                                   // [B,T,S]
  float* out2 = attn + (size_t)B_DIM * T_DIM * S_DIM;            // [B,C,T]

  transpose_wh2e<<<dim3(C_DIM / 32, E_DIM / 32), dim3(32, 8)>>>(w_h2e);
  gemm1_kernel<<<dim3(E_DIM / BN, T_DIM / BM, B_DIM), 256>>>(conved, x, b_h2e, scale);
  gemm2_kernel<<<dim3(S_DIM / BN, T_DIM / BM, B_DIM), 256>>>(enc_conved, attn);
  softmax_kernel<<<B_DIM * T_DIM, 256>>>(attn);
  gemm3_kernel<<<dim3(E_DIM / BN, T_DIM / BM, B_DIM), 256>>>(enc_combined, attn);
  gemm4_kernel<<<dim3(T_DIM / BN, C_DIM / BM, B_DIM), 256>>>(w_e2h, b_e2h, conved, out2);
}

// round 4
// speedup vs baseline: 2.3746x; 2.3746x over previous
#include <cuda_runtime.h>
#include <cuda_bf16.h>
#include <cstdint>

#define B_DIM 8
#define C_DIM 2048
#define T_DIM 1024
#define S_DIM 1024
#define E_DIM 1024

// Block tile 128x128, BK=32 (bf16), 256 threads = 8 warps as 4(M) x 2(N),
// warp tile 32x64, mma.sync.m16n8k16 bf16, 3-term (hi*hi + hi*lo + lo*hi).

// SMEM: 2 stages x 4 arrays (Ahi,Alo,Bhi,Blo), each 128 rows x 64B = 8192B.
#define STAGE_BYTES 32768
#define SMEM_SZ (2 * STAGE_BYTES)

// Device-global scratch (allocation-free rule), bf16 splits. ~230 MB.
__device__ __nv_bfloat16 g_cT_hi[(size_t)B_DIM * T_DIM * C_DIM];  // conved^T [b][t][c]
__device__ __nv_bfloat16 g_cT_lo[(size_t)B_DIM * T_DIM * C_DIM];
__device__ __nv_bfloat16 g_whe_hi[(size_t)E_DIM * C_DIM];         // w_h2e [e][c]
__device__ __nv_bfloat16 g_whe_lo[(size_t)E_DIM * C_DIM];
__device__ __nv_bfloat16 g_Y_hi[(size_t)B_DIM * T_DIM * E_DIM];   // Y [b][t][e]
__device__ __nv_bfloat16 g_Y_lo[(size_t)B_DIM * T_DIM * E_DIM];
__device__ __nv_bfloat16 g_ec_hi[(size_t)B_DIM * S_DIM * E_DIM];  // enc_conved [b][s][e]
__device__ __nv_bfloat16 g_ec_lo[(size_t)B_DIM * S_DIM * E_DIM];
__device__ __nv_bfloat16 g_at_hi[(size_t)B_DIM * T_DIM * S_DIM];  // attention [b][t][s]
__device__ __nv_bfloat16 g_at_lo[(size_t)B_DIM * T_DIM * S_DIM];
__device__ __nv_bfloat16 g_eT_hi[(size_t)B_DIM * E_DIM * S_DIM];  // enc_combined^T [b][e][s]
__device__ __nv_bfloat16 g_eT_lo[(size_t)B_DIM * E_DIM * S_DIM];
__device__ __nv_bfloat16 g_A2_hi[(size_t)B_DIM * T_DIM * E_DIM];  // attended [b][t][e]
__device__ __nv_bfloat16 g_A2_lo[(size_t)B_DIM * T_DIM * E_DIM];
__device__ __nv_bfloat16 g_weh_hi[(size_t)C_DIM * E_DIM];         // w_e2h [c][e]
__device__ __nv_bfloat16 g_weh_lo[(size_t)C_DIM * E_DIM];

// ---------------------------------------------------------------------------
// Helpers
// ---------------------------------------------------------------------------
__device__ __forceinline__ void split2(float v, __nv_bfloat16& h, __nv_bfloat16& l) {
  h = __float2bfloat16(v);
  l = __float2bfloat16(v - __bfloat162float(h));
}

__device__ __forceinline__ uint32_t smem_u32(const void* p) {
  uint32_t a;
  asm("{ .reg .u64 t; cvta.to.shared.u64 t, %1; cvt.u32.u64 %0, t; }" : "=r"(a) : "l"(p));
  return a;
}

__device__ __forceinline__ void cp16(uint32_t dst, const void* src) {
  asm volatile("cp.async.cg.shared.global [%0], [%1], 16;\n" ::"r"(dst), "l"(src));
}
__device__ __forceinline__ void cp_commit() { asm volatile("cp.async.commit_group;\n" ::); }
__device__ __forceinline__ void cp_wait1() { asm volatile("cp.async.wait_group 1;\n" ::); }
__device__ __forceinline__ void cp_wait0() { asm volatile("cp.async.wait_group 0;\n" ::); }

__device__ __forceinline__ void ldsm4(uint32_t* r, uint32_t addr) {
  asm volatile("ldmatrix.sync.aligned.m8n8.x4.shared.b16 {%0,%1,%2,%3}, [%4];"
               : "=r"(r[0]), "=r"(r[1]), "=r"(r[2]), "=r"(r[3]) : "r"(addr));
}

__device__ __forceinline__ void mma_bf16(float* c, const uint32_t* a, const uint32_t* b) {
  asm volatile(
      "mma.sync.aligned.m16n8k16.row.col.f32.bf16.bf16.f32 "
      "{%0,%1,%2,%3}, {%4,%5,%6,%7}, {%8,%9}, {%0,%1,%2,%3};"
      : "+f"(c[0]), "+f"(c[1]), "+f"(c[2]), "+f"(c[3])
      : "r"(a[0]), "r"(a[1]), "r"(a[2]), "r"(a[3]), "r"(b[0]), "r"(b[1]));
}

// 16B-segment swizzle within a 64B row: bijective over the 8-row ldmatrix phase.
__device__ __forceinline__ uint32_t sw_off(int row, int seg) {
  return (uint32_t)(row * 64 + ((seg ^ ((row >> 1) & 3)) << 4));
}

// ---------------------------------------------------------------------------
// Pre-pass: elementwise split f32 -> (bf16 hi, bf16 lo)
// ---------------------------------------------------------------------------
__global__ void split_ew(const float* __restrict__ src, __nv_bfloat16* __restrict__ hi,
                         __nv_bfloat16* __restrict__ lo, int n4) {
  int i = blockIdx.x * blockDim.x + threadIdx.x;
  if (i >= n4) return;
  float4 a = reinterpret_cast<const float4*>(src)[i];
  __nv_bfloat16 h[4], l[4];
  split2(a.x, h[0], l[0]); split2(a.y, h[1], l[1]);
  split2(a.z, h[2], l[2]); split2(a.w, h[3], l[3]);
  reinterpret_cast<uint2*>(hi)[i] = *reinterpret_cast<uint2*>(h);
  reinterpret_cast<uint2*>(lo)[i] = *reinterpret_cast<uint2*>(l);
}

// ---------------------------------------------------------------------------
// Pre-pass: transpose + split. src [z][R][Cc] f32 -> hi/lo [z][Cc][R] bf16
// ---------------------------------------------------------------------------
__global__ void transpose_split(const float* __restrict__ src, __nv_bfloat16* __restrict__ hi,
                                __nv_bfloat16* __restrict__ lo, int R, int Cc) {
  __shared__ float tile[32][33];
  const int c0 = blockIdx.x * 32, r0 = blockIdx.y * 32, z = blockIdx.z;
  const int tx = threadIdx.x, ty = threadIdx.y;
  const float* s = src + (size_t)z * R * Cc;
#pragma unroll
  for (int i = 0; i < 32; i += 8)
    tile[ty + i][tx] = s[(size_t)(r0 + ty + i) * Cc + c0 + tx];
  __syncthreads();
  __nv_bfloat16* H = hi + (size_t)z * R * Cc;
  __nv_bfloat16* L = lo + (size_t)z * R * Cc;
#pragma unroll
  for (int i = 0; i < 32; i += 8) {
    float v = tile[tx][ty + i];
    __nv_bfloat16 h, l;
    split2(v, h, l);
    H[(size_t)(c0 + ty + i) * R + r0 + tx] = h;
    L[(size_t)(c0 + ty + i) * R + r0 + tx] = l;
  }
}

// ---------------------------------------------------------------------------
// Softmax over S, in place; also emits bf16 hi/lo splits.
// ---------------------------------------------------------------------------
__global__ __launch_bounds__(256) void softmax_kernel(float* __restrict__ att,
                                                      __nv_bfloat16* __restrict__ hi,
                                                      __nv_bfloat16* __restrict__ lo) {
  const size_t row = blockIdx.x;
  float* p = att + row * S_DIM;
  const int tid = threadIdx.x;
  float4 v = reinterpret_cast<float4*>(p)[tid];

  float m = fmaxf(fmaxf(v.x, v.y), fmaxf(v.z, v.w));
#pragma unroll
  for (int o = 16; o; o >>= 1) m = fmaxf(m, __shfl_xor_sync(0xffffffffu, m, o));
  __shared__ float redm[8];
  if ((tid & 31) == 0) redm[tid >> 5] = m;
  __syncthreads();
  float mall = redm[0];
#pragma unroll
  for (int i = 1; i < 8; ++i) mall = fmaxf(mall, redm[i]);

  v.x = __expf(v.x - mall); v.y = __expf(v.y - mall);
  v.z = __expf(v.z - mall); v.w = __expf(v.w - mall);
  float s = v.x + v.y + v.z + v.w;
#pragma unroll
  for (int o = 16; o; o >>= 1) s += __shfl_xor_sync(0xffffffffu, s, o);
  __shared__ float reds[8];
  if ((tid & 31) == 0) reds[tid >> 5] = s;
  __syncthreads();
  float sall = 0.f;
#pragma unroll
  for (int i = 0; i < 8; ++i) sall += reds[i];
  const float inv = 1.0f / sall;
  v.x *= inv; v.y *= inv; v.z *= inv; v.w *= inv;
  reinterpret_cast<float4*>(p)[tid] = v;

  __nv_bfloat16 h[4], l[4];
  split2(v.x, h[0], l[0]); split2(v.y, h[1], l[1]);
  split2(v.z, h[2], l[2]); split2(v.w, h[3], l[3]);
  reinterpret_cast<uint2*>(hi + row * S_DIM)[tid] = *reinterpret_cast<uint2*>(h);
  reinterpret_cast<uint2*>(lo + row * S_DIM)[tid] = *reinterpret_cast<uint2*>(l);
}

// ---------------------------------------------------------------------------
// bf16x3 NT GEMM via mma.sync: D[m,n] = sum_k A[m,k]*B[n,k].
// MODE 1: Y = (D + b_h2e[n] + x[b,m,n]) * scale  -> split (oh, ol)
// MODE 2: energy -> out0 (f32)
// MODE 3: attended -> split (oh, ol)
// MODE 4: out0 = D + conved[b,m,n] + b_e2h[m]
// ---------------------------------------------------------------------------
template <int MODE, int K_TOT, int SA, int SB>
__global__ __launch_bounds__(256, 1) void gemm_mma(
    const __nv_bfloat16* __restrict__ Ahi, const __nv_bfloat16* __restrict__ Alo,
    const __nv_bfloat16* __restrict__ Bhi, const __nv_bfloat16* __restrict__ Blo,
    float* __restrict__ out0, __nv_bfloat16* __restrict__ oh, __nv_bfloat16* __restrict__ ol,
    const float* __restrict__ e0, const float* __restrict__ e1,
    const float* __restrict__ scale_p) {
  extern __shared__ char smem[];
  const uint32_t sb = smem_u32(smem);
  const int tid = threadIdx.x;
  const int wid = tid >> 5, lane = tid & 31;
  const int wm = wid >> 1, wn = wid & 1;  // 4 x 2 warp grid
  const int mblk = blockIdx.y * 128;
  const int nblk = blockIdx.x * 128;
  const int b = blockIdx.z;

  const __nv_bfloat16* Ah = Ahi + (size_t)b * SA + (size_t)mblk * K_TOT;
  const __nv_bfloat16* Al = Alo + (size_t)b * SA + (size_t)mblk * K_TOT;
  const __nv_bfloat16* Bh = Bhi + (size_t)b * SB + (size_t)nblk * K_TOT;
  const __nv_bfloat16* Bl = Blo + (size_t)b * SB + (size_t)nblk * K_TOT;

  float acc[64];
#pragma unroll
  for (int i = 0; i < 64; ++i) acc[i] = 0.f;

  auto load_chunk = [&](int k0, int st) {
    const uint32_t base = sb + st * STAGE_BYTES;
#pragma unroll
    for (int it = 0; it < 2; ++it) {
      const int c = tid + it * 256;        // 0..511
      const int row = c >> 2, seg = c & 3;
      const uint32_t sw = sw_off(row, seg);
      const size_t g = (size_t)row * K_TOT + k0 + seg * 8;
      cp16(base + sw, Ah + g);
      cp16(base + 8192 + sw, Al + g);
      cp16(base + 16384 + sw, Bh + g);
      cp16(base + 24576 + sw, Bl + g);
    }
  };

  // ldmatrix lane address pieces (rows are tile-local 0..127)
  const int a_row_l = (lane & 15);         // + wm*32 + mt*16
  const int a_kh = lane >> 4;              // 0/1
  const int b_row_l = ((lane >> 4) << 3) + (lane & 7);  // + wn*64 + pair*16
  const int b_kh = (lane >> 3) & 1;

  const int nch = K_TOT / 32;
  load_chunk(0, 0);
  cp_commit();

  for (int i = 0; i < nch; ++i) {
    const int st = i & 1;
    if (i + 1 < nch) {
      load_chunk((i + 1) * 32, st ^ 1);
      cp_commit();
      cp_wait1();
    } else {
      cp_wait0();
    }
    __syncthreads();

    const uint32_t aH = sb + st * STAGE_BYTES;
    const uint32_t aL = aH + 8192;
    const uint32_t bH = aH + 16384;
    const uint32_t bL = aH + 24576;
#pragma unroll
    for (int ks = 0; ks < 2; ++ks) {
      uint32_t afh[2][4], afl[2][4];
      const int segA = ks * 2 + a_kh;
#pragma unroll
      for (int mt = 0; mt < 2; ++mt) {
        const int row = wm * 32 + mt * 16 + a_row_l;
        const uint32_t off = sw_off(row, segA);
        ldsm4(afh[mt], aH + off);
        ldsm4(afl[mt], aL + off);
      }
      uint32_t bfh[8][2], bfl[8][2];
      const int segB = ks * 2 + b_kh;
#pragma unroll
      for (int pr = 0; pr < 4; ++pr) {
        const int row = wn * 64 + pr * 16 + b_row_l;
        const uint32_t off = sw_off(row, segB);
        uint32_t r4[4];
        ldsm4(r4, bH + off);
        bfh[pr * 2][0] = r4[0]; bfh[pr * 2][1] = r4[1];
        bfh[pr * 2 + 1][0] = r4[2]; bfh[pr * 2 + 1][1] = r4[3];
        ldsm4(r4, bL + off);
        bfl[pr * 2][0] = r4[0]; bfl[pr * 2][1] = r4[1];
        bfl[pr * 2 + 1][0] = r4[2]; bfl[pr * 2 + 1][1] = r4[3];
      }
#pragma unroll
      for (int mt = 0; mt < 2; ++mt)
#pragma unroll
        for (int nt = 0; nt < 8; ++nt) {
          float* c = acc + mt * 32 + nt * 4;
          mma_bf16(c, afh[mt], bfh[nt]);
          mma_bf16(c, afh[mt], bfl[nt]);
          mma_bf16(c, afl[mt], bfh[nt]);
        }
    }
    __syncthreads();
  }

  // Epilogue. Fragment: {c0,c1} at row (lane>>2), cols cpair; {c2,c3} at row+8.
  const int rbase = lane >> 2;
  const int cpair = (lane & 3) * 2;
#pragma unroll
  for (int mt = 0; mt < 2; ++mt) {
#pragma unroll
    for (int nt = 0; nt < 8; ++nt) {
      const float* c = acc + mt * 32 + nt * 4;
      const int n = nblk + wn * 64 + nt * 8 + cpair;
#pragma unroll
      for (int hh = 0; hh < 2; ++hh) {
        const int m = mblk + wm * 32 + mt * 16 + rbase + hh * 8;
        const float v0 = c[hh * 2 + 0], v1 = c[hh * 2 + 1];
        if constexpr (MODE == 1) {
          const float s = scale_p[0];
          const size_t off = (size_t)b * T_DIM * E_DIM + (size_t)m * E_DIM + n;
          const float2 xv = *(const float2*)(e0 + off);
          const float2 bv = *(const float2*)(e1 + n);
          const float y0 = (v0 + bv.x + xv.x) * s;
          const float y1 = (v1 + bv.y + xv.y) * s;
          __nv_bfloat16 h0, l0, h1, l1;
          split2(y0, h0, l0); split2(y1, h1, l1);
          __nv_bfloat162 hp, lp;
          hp.x = h0; hp.y = h1; lp.x = l0; lp.y = l1;
          *(__nv_bfloat162*)(oh + off) = hp;
          *(__nv_bfloat162*)(ol + off) = lp;
        } else if constexpr (MODE == 2) {
          const size_t off = (size_t)b * T_DIM * S_DIM + (size_t)m * S_DIM + n;
          float2 o; o.x = v0; o.y = v1;
          *(float2*)(out0 + off) = o;
        } else if constexpr (MODE == 3) {
          const size_t off = (size_t)b * T_DIM * E_DIM + (size_t)m * E_DIM + n;
          __nv_bfloat16 h0, l0, h1, l1;
          split2(v0, h0, l0); split2(v1, h1, l1);
          __nv_bfloat162 hp, lp;
          hp.x = h0; hp.y = h1; lp.x = l0; lp.y = l1;
          *(__nv_bfloat162*)(oh + off) = hp;
          *(__nv_bfloat162*)(ol + off) = lp;
        } else {  // MODE 4
          const float bias = __ldg(e1 + m);
          const size_t off = (size_t)b * C_DIM * T_DIM + (size_t)m * T_DIM + n;
          const float2 cv = *(const float2*)(e0 + off);
          float2 o;
          o.x = v0 + cv.x + bias;
          o.y = v1 + cv.y + bias;
          *(float2*)(out0 + off) = o;
        }
      }
    }
  }
}

// ---------------------------------------------------------------------------
// Launch
// ---------------------------------------------------------------------------
extern "C" void kernel_launch(void* const* d_in, const int* in_sizes, int n_in,
                              void* d_out, int out_size) {
  const float* conved       = (const float*)d_in[0];
  const float* enc_conved   = (const float*)d_in[1];
  const float* enc_combined = (const float*)d_in[2];
  const float* x            = (const float*)d_in[3];
  const float* scale        = (const float*)d_in[4];
  const float* w_h2e        = (const float*)d_in[5];
  const float* b_h2e        = (const float*)d_in[6];
  const float* w_e2h        = (const float*)d_in[7];
  const float* b_e2h        = (const float*)d_in[8];

  float* attn = (float*)d_out;                          // [B,T,S]
  float* out2 = attn + (size_t)B_DIM * T_DIM * S_DIM;   // [B,C,T]

  __nv_bfloat16 *cT_hi, *cT_lo, *whe_hi, *whe_lo, *Y_hi, *Y_lo, *ec_hi, *ec_lo,
      *at_hi, *at_lo, *eT_hi, *eT_lo, *A2_hi, *A2_lo, *weh_hi, *weh_lo;
  cudaGetSymbolAddress((void**)&cT_hi, g_cT_hi);
  cudaGetSymbolAddress((void**)&cT_lo, g_cT_lo);
  cudaGetSymbolAddress((void**)&whe_hi, g_whe_hi);
  cudaGetSymbolAddress((void**)&whe_lo, g_whe_lo);
  cudaGetSymbolAddress((void**)&Y_hi, g_Y_hi);
  cudaGetSymbolAddress((void**)&Y_lo, g_Y_lo);
  cudaGetSymbolAddress((void**)&ec_hi, g_ec_hi);
  cudaGetSymbolAddress((void**)&ec_lo, g_ec_lo);
  cudaGetSymbolAddress((void**)&at_hi, g_at_hi);
  cudaGetSymbolAddress((void**)&at_lo, g_at_lo);
  cudaGetSymbolAddress((void**)&eT_hi, g_eT_hi);
  cudaGetSymbolAddress((void**)&eT_lo, g_eT_lo);
  cudaGetSymbolAddress((void**)&A2_hi, g_A2_hi);
  cudaGetSymbolAddress((void**)&A2_lo, g_A2_lo);
  cudaGetSymbolAddress((void**)&weh_hi, g_weh_hi);
  cudaGetSymbolAddress((void**)&weh_lo, g_weh_lo);

  cudaFuncSetAttribute(gemm_mma<1, C_DIM, T_DIM * C_DIM, 0>,
                       cudaFuncAttributeMaxDynamicSharedMemorySize, SMEM_SZ);
  cudaFuncSetAttribute(gemm_mma<2, E_DIM, T_DIM * E_DIM, S_DIM * E_DIM>,
                       cudaFuncAttributeMaxDynamicSharedMemorySize, SMEM_SZ);
  cudaFuncSetAttribute(gemm_mma<3, S_DIM, T_DIM * S_DIM, E_DIM * S_DIM>,
                       cudaFuncAttributeMaxDynamicSharedMemorySize, SMEM_SZ);
  cudaFuncSetAttribute(gemm_mma<4, E_DIM, 0, T_DIM * E_DIM>,
                       cudaFuncAttributeMaxDynamicSharedMemorySize, SMEM_SZ);

  // Pre-passes
  transpose_split<<<dim3(T_DIM / 32, C_DIM / 32, B_DIM), dim3(32, 8)>>>(
      conved, cT_hi, cT_lo, C_DIM, T_DIM);
  transpose_split<<<dim3(E_DIM / 32, S_DIM / 32, B_DIM), dim3(32, 8)>>>(
      enc_combined, eT_hi, eT_lo, S_DIM, E_DIM);
  split_ew<<<(E_DIM * C_DIM / 4 + 255) / 256, 256>>>(w_h2e, whe_hi, whe_lo, E_DIM * C_DIM / 4);
  split_ew<<<((int)((size_t)B_DIM * S_DIM * E_DIM / 4) + 255) / 256, 256>>>(
      enc_conved, ec_hi, ec_lo, (int)((size_t)B_DIM * S_DIM * E_DIM / 4));
  split_ew<<<(C_DIM * E_DIM / 4 + 255) / 256, 256>>>(w_e2h, weh_hi, weh_lo, C_DIM * E_DIM / 4);

  // GEMM1: Y = (conved^T @ w_h2e^T + b + x) * scale  -> split
  gemm_mma<1, C_DIM, T_DIM * C_DIM, 0>
      <<<dim3(E_DIM / 128, T_DIM / 128, B_DIM), 256, SMEM_SZ>>>(
          cT_hi, cT_lo, whe_hi, whe_lo, nullptr, Y_hi, Y_lo, x, b_h2e, scale);
  // GEMM2: energy -> d_out attention region
  gemm_mma<2, E_DIM, T_DIM * E_DIM, S_DIM * E_DIM>
      <<<dim3(S_DIM / 128, T_DIM / 128, B_DIM), 256, SMEM_SZ>>>(
          Y_hi, Y_lo, ec_hi, ec_lo, attn, nullptr, nullptr, nullptr, nullptr, nullptr);
  // Softmax in place; emit splits
  softmax_kernel<<<B_DIM * T_DIM, 256>>>(attn, at_hi, at_lo);
  // GEMM3: attended -> split
  gemm_mma<3, S_DIM, T_DIM * S_DIM, E_DIM * S_DIM>
      <<<dim3(E_DIM / 128, T_DIM / 128, B_DIM), 256, SMEM_SZ>>>(
          at_hi, at_lo, eT_hi, eT_lo, nullptr, A2_hi, A2_lo, nullptr, nullptr, nullptr);
  // GEMM4: out2 = w_e2h @ A2^T + conved + bias
  gemm_mma<4, E_DIM, 0, T_DIM * E_DIM>
      <<<dim3(T_DIM / 128, C_DIM / 128, B_DIM), 256, SMEM_SZ>>>(
          weh_hi, weh_lo, A2_hi, A2_lo, out2, nullptr, nullptr, conved, b_e2h, nullptr);
}